// round 1
// baseline (speedup 1.0000x reference)
#include <cuda_runtime.h>
#include <math.h>

#define BB 64
#define JJ 512
#define DD 1024
#define NTOK (BB*JJ)

// Scratch (allocation-free rule: __device__ globals)
__device__ float g_valpre[NTOK];
__device__ float g_att[NTOK];
__device__ float g_pooled[BB*DD];

// ---------------------------------------------------------------------------
// Kernel 1: fused scoring GEMM.
// valpre[t] = sum_e tanh( sum_d x[t,d]*W1[d,e] + b1[e] ) * W2[e]
// Block = 64 tokens; loops over all 16 e-tiles of 64; BK=16; 256 threads,
// 4x4 micro-tile per thread. No h materialization, no atomics.
// ---------------------------------------------------------------------------
#define BM 64
#define BN 64
#define BK 16

__global__ __launch_bounds__(256) void k_score(const float* __restrict__ x,
                                               const float* __restrict__ W1,
                                               const float* __restrict__ b1,
                                               const float* __restrict__ W2)
{
    __shared__ float As[BK][BM];
    __shared__ float Bs[BK][BN];
    __shared__ float red[BM][17];

    const int tid = threadIdx.x;
    const int tx = tid & 15;        // e micro-tile index
    const int ty = tid >> 4;        // token micro-tile index
    const int tokBase = blockIdx.x * BM;

    // loader mapping
    const int la_t = tid >> 2;            // 0..63 token in tile
    const int la_k = (tid & 3) * 4;       // 0,4,8,12
    const int lb_k = tid >> 4;            // 0..15
    const int lb_e = (tid & 15) * 4;      // 0..60

    float tokAcc[4] = {0.f, 0.f, 0.f, 0.f};

    for (int eb = 0; eb < DD; eb += BN) {
        float acc[4][4];
#pragma unroll
        for (int i = 0; i < 4; i++)
#pragma unroll
            for (int j = 0; j < 4; j++) acc[i][j] = 0.f;

        for (int kb = 0; kb < DD; kb += BK) {
            __syncthreads();
            // A tile (x), stored transposed As[k][t]
            float4 a4 = *reinterpret_cast<const float4*>(
                &x[(size_t)(tokBase + la_t) * DD + kb + la_k]);
            As[la_k + 0][la_t] = a4.x;
            As[la_k + 1][la_t] = a4.y;
            As[la_k + 2][la_t] = a4.z;
            As[la_k + 3][la_t] = a4.w;
            // B tile (W1)
            *reinterpret_cast<float4*>(&Bs[lb_k][lb_e]) =
                *reinterpret_cast<const float4*>(
                    &W1[(size_t)(kb + lb_k) * DD + eb + lb_e]);
            __syncthreads();

#pragma unroll
            for (int k = 0; k < BK; k++) {
                float4 ra = *reinterpret_cast<float4*>(&As[k][ty * 4]);
                float4 rb = *reinterpret_cast<float4*>(&Bs[k][tx * 4]);
                float av[4] = {ra.x, ra.y, ra.z, ra.w};
                float bv[4] = {rb.x, rb.y, rb.z, rb.w};
#pragma unroll
                for (int i = 0; i < 4; i++)
#pragma unroll
                    for (int j = 0; j < 4; j++)
                        acc[i][j] += av[i] * bv[j];
            }
        }

        // e-tile epilogue: tanh + weight by W2, fold into per-token scalar
#pragma unroll
        for (int j = 0; j < 4; j++) {
            int e = eb + tx * 4 + j;
            float be = __ldg(&b1[e]);
            float w2 = __ldg(&W2[e]);
#pragma unroll
            for (int i = 0; i < 4; i++) {
                float h = tanhf(acc[i][j] + be);
                tokAcc[i] += h * w2;
            }
        }
    }

    // reduce the 16 tx-partials per token
    __syncthreads();
#pragma unroll
    for (int i = 0; i < 4; i++) red[ty * 4 + i][tx] = tokAcc[i];
    __syncthreads();
    if (tid < BM) {
        float s = 0.f;
#pragma unroll
        for (int c = 0; c < 16; c++) s += red[tid][c];
        g_valpre[tokBase + tid] = s;
    }
}

// ---------------------------------------------------------------------------
// Kernel 2: sigmoid + mask + per-batch normalization; writes att_weights.
// One block per batch (512 threads = J tokens).
// ---------------------------------------------------------------------------
__global__ __launch_bounds__(512) void k_finalize(const float* __restrict__ mask,
                                                  const float* __restrict__ b2,
                                                  float* __restrict__ out_att)
{
    __shared__ float sred[16];
    const int b = blockIdx.x;
    const int j = threadIdx.x;

    float v = g_valpre[b * JJ + j];
    v = 1.f / (1.f + __expf(-(v + b2[0])));
    v *= mask[b * JJ + j];

    float s = v;
#pragma unroll
    for (int o = 16; o; o >>= 1) s += __shfl_xor_sync(0xffffffffu, s, o);
    if ((j & 31) == 0) sred[j >> 5] = s;
    __syncthreads();
    if (j < 16) {
        float t = sred[j];
#pragma unroll
        for (int o = 8; o; o >>= 1) t += __shfl_xor_sync(0xffffu, t, o);
        if (j == 0) sred[0] = t;
    }
    __syncthreads();

    float a = v * (1.f / sred[0]);
    g_att[b * JJ + j] = a;
    out_att[b * JJ + j] = a;   // att_weights output
}

// ---------------------------------------------------------------------------
// Kernel 3: pooled[b,d] = sum_j x[b,j,d] * att[b,j]
// grid (chunks=4, B); 256 threads each own one d.
// ---------------------------------------------------------------------------
__global__ __launch_bounds__(256) void k_pool(const float* __restrict__ x)
{
    __shared__ float sa[JJ];
    const int b = blockIdx.y;
    const int d = blockIdx.x * 256 + threadIdx.x;

    for (int j = threadIdx.x; j < JJ; j += 256) sa[j] = g_att[b * JJ + j];
    __syncthreads();

    float acc = 0.f;
    const float* xb = x + (size_t)b * JJ * DD + d;
#pragma unroll 8
    for (int j = 0; j < JJ; j++) acc += xb[(size_t)j * DD] * sa[j];
    g_pooled[b * DD + d] = acc;
}

// ---------------------------------------------------------------------------
// Kernel 4: output[b,:] = pooled[b,:] @ W3 + b3   (1024x3)
// One block per batch.
// ---------------------------------------------------------------------------
__global__ __launch_bounds__(128) void k_out(const float* __restrict__ W3,
                                             const float* __restrict__ b3,
                                             float* __restrict__ out)
{
    __shared__ float sred[3][4];
    const int b = blockIdx.x;
    const int t = threadIdx.x;

    float a0 = 0.f, a1 = 0.f, a2 = 0.f;
    for (int d = t; d < DD; d += 128) {
        float p = g_pooled[b * DD + d];
        a0 += p * W3[d * 3 + 0];
        a1 += p * W3[d * 3 + 1];
        a2 += p * W3[d * 3 + 2];
    }
#pragma unroll
    for (int o = 16; o; o >>= 1) {
        a0 += __shfl_xor_sync(0xffffffffu, a0, o);
        a1 += __shfl_xor_sync(0xffffffffu, a1, o);
        a2 += __shfl_xor_sync(0xffffffffu, a2, o);
    }
    const int w = t >> 5;
    if ((t & 31) == 0) { sred[0][w] = a0; sred[1][w] = a1; sred[2][w] = a2; }
    __syncthreads();
    if (t == 0) {
        float r0 = 0.f, r1 = 0.f, r2 = 0.f;
#pragma unroll
        for (int k = 0; k < 4; k++) { r0 += sred[0][k]; r1 += sred[1][k]; r2 += sred[2][k]; }
        out[b * 3 + 0] = r0 + b3[0];
        out[b * 3 + 1] = r1 + b3[1];
        out[b * 3 + 2] = r2 + b3[2];
    }
}

// ---------------------------------------------------------------------------
extern "C" void kernel_launch(void* const* d_in, const int* in_sizes, int n_in,
                              void* d_out, int out_size)
{
    const float* x    = (const float*)d_in[0];
    const float* mask = (const float*)d_in[1];
    const float* W1   = (const float*)d_in[2];
    const float* b1   = (const float*)d_in[3];
    const float* W2   = (const float*)d_in[4];
    const float* b2   = (const float*)d_in[5];
    const float* W3   = (const float*)d_in[6];
    const float* b3   = (const float*)d_in[7];
    float* out = (float*)d_out;

    float* out_val = out;                 // [64,3]
    float* out_att = out + BB * 3;        // [64,512,1]

    k_score<<<NTOK / BM, 256>>>(x, W1, b1, W2);
    k_finalize<<<BB, 512>>>(mask, b2, out_att);
    dim3 gpool(DD / 256, BB);
    k_pool<<<gpool, 256>>>(x);
    k_out<<<BB, 128>>>(W3, b3, out_val);
}

// round 3
// speedup vs baseline: 1.9467x; 1.9467x over previous
#include <cuda_runtime.h>
#include <math.h>
#include <mma.h>
#include <cstdint>

using namespace nvcuda;

#define BB 64
#define JJ 512
#define DD 1024
#define NTOK (BB*JJ)

// Scratch (allocation-free rule: __device__ globals)
__device__ float g_valpre[NTOK];
__device__ float g_att[NTOK];
__device__ float g_pooled[BB*DD];

// ---------------------------------------------------------------------------
// cp.async helpers (sm_80 baseline features -> compile for compute_103)
// ---------------------------------------------------------------------------
__device__ __forceinline__ uint32_t smem_u32(const void* p) {
    uint32_t a;
    asm("{ .reg .u64 t; cvta.to.shared.u64 t, %1; cvt.u32.u64 %0, t; }" : "=r"(a) : "l"(p));
    return a;
}
#define CP_ASYNC16(s, g) asm volatile("cp.async.cg.shared.global [%0], [%1], 16;" :: "r"(s), "l"(g) : "memory")
#define CP_COMMIT()      asm volatile("cp.async.commit_group;" ::: "memory")
#define CP_WAIT1()       asm volatile("cp.async.wait_group 1;" ::: "memory")
#define CP_WAIT0()       asm volatile("cp.async.wait_group 0;" ::: "memory")

// accurate tanh via expf (rel err ~1e-6)
__device__ __forceinline__ float tanh_fast(float x) {
    float z = __expf(-2.f * fabsf(x));
    float t = __fdividef(1.f - z, 1.f + z);
    return copysignf(t, x);
}

// ---------------------------------------------------------------------------
// Kernel 1: WMMA tf32 scoring GEMM + fused tanh/W2 epilogue.
// CTA: 128 tokens x 128 e-cols/pass, 8 n-tile passes, K chunks of 32.
// 8 warps (4m x 2n), warp tile 32x64 = 2x4 m16n16k8 fragments.
// valpre[t] = sum_e tanh( (x @ W1)[t,e] + b1[e] ) * W2[e]
// ---------------------------------------------------------------------------
#define M_CTA 128
#define N_TILE 128
#define K_CHUNK 32
#define A_LD 36              // floats (32 + 4 pad)
#define B_LD 132             // floats (128 + 4 pad)
#define A_STAGE_B (M_CTA * A_LD * 4)              // 18432
#define B_STAGE_B (K_CHUNK * B_LD * 4)            // 16896
#define STAGE_B   (A_STAGE_B + B_STAGE_B)         // 35328
#define PATCH_LD 20

typedef wmma::fragment<wmma::matrix_a, 16, 16, 8, wmma::precision::tf32, wmma::row_major> FragA;
typedef wmma::fragment<wmma::matrix_b, 16, 16, 8, wmma::precision::tf32, wmma::row_major> FragB;
typedef wmma::fragment<wmma::accumulator, 16, 16, 8, float> FragC;

__device__ __forceinline__ void prefetchA(uint32_t As_u, const float* __restrict__ x,
                                          int tokBase, int kb, int tid) {
#pragma unroll
    for (int i = 0; i < 4; i++) {
        int c = tid + i * 256;
        int row = c >> 3, q = c & 7;
        CP_ASYNC16(As_u + row * (A_LD * 4) + q * 16,
                   x + (size_t)(tokBase + row) * DD + kb + q * 4);
    }
}
__device__ __forceinline__ void prefetchB(uint32_t Bs_u, const float* __restrict__ W1,
                                          int eb, int kb, int tid) {
#pragma unroll
    for (int i = 0; i < 4; i++) {
        int c = tid + i * 256;
        int row = c >> 5, q = c & 31;
        CP_ASYNC16(Bs_u + row * (B_LD * 4) + q * 16,
                   W1 + (size_t)(kb + row) * DD + eb + q * 4);
    }
}

__global__ void __launch_bounds__(256, 2)
k_score_mma(const float* __restrict__ x, const float* __restrict__ W1,
            const float* __restrict__ b1, const float* __restrict__ W2)
{
    extern __shared__ __align__(16) char dsm[];           // 2 stages
    __shared__ float s_b1[DD];
    __shared__ float s_w2[DD];
    __shared__ __align__(16) float s_patch[8 * 16 * PATCH_LD];
    __shared__ float s_val[2][M_CTA];

    const int tid = threadIdx.x;
    const int wid = tid >> 5;
    const int lane = tid & 31;
    const int warp_m = wid >> 1;          // 0..3
    const int warp_n = wid & 1;           // 0..1
    const int tokBase = blockIdx.x * M_CTA;

    const uint32_t dsm_u = smem_u32(dsm);

    for (int i = tid; i < DD; i += 256) { s_b1[i] = b1[i]; s_w2[i] = W2[i]; }

    float* patch = s_patch + wid * 16 * PATCH_LD;
    float tokAcc[2] = {0.f, 0.f};

    // prologue: n-tile 0, chunk 0 -> stage 0
    prefetchA(dsm_u, x, tokBase, 0, tid);
    prefetchB(dsm_u + A_STAGE_B, W1, 0, 0, tid);
    CP_COMMIT();

    for (int nt = 0; nt < 8; nt++) {
        const int eb = nt * N_TILE;

        FragC acc[2][4];
#pragma unroll
        for (int fm = 0; fm < 2; fm++)
#pragma unroll
            for (int fn = 0; fn < 4; fn++)
                wmma::fill_fragment(acc[fm][fn], 0.f);

        for (int kc = 0; kc < 32; kc++) {
            const uint32_t st = (uint32_t)(kc & 1) * STAGE_B;
            if (kc < 31) {
                const uint32_t nst = (uint32_t)((kc + 1) & 1) * STAGE_B;
                prefetchA(dsm_u + nst, x, tokBase, (kc + 1) * K_CHUNK, tid);
                prefetchB(dsm_u + nst + A_STAGE_B, W1, eb, (kc + 1) * K_CHUNK, tid);
                CP_COMMIT();
                CP_WAIT1();
            } else {
                CP_WAIT0();
            }
            __syncthreads();

            const float* As_f = (const float*)(dsm + st);
            const float* Bs_f = (const float*)(dsm + st + A_STAGE_B);

#pragma unroll
            for (int kk = 0; kk < 4; kk++) {
                FragA a[2];
#pragma unroll
                for (int fm = 0; fm < 2; fm++) {
                    wmma::load_matrix_sync(a[fm],
                        As_f + (warp_m * 32 + fm * 16) * A_LD + kk * 8, A_LD);
#pragma unroll
                    for (int t = 0; t < a[fm].num_elements; t++)
                        a[fm].x[t] = wmma::__float_to_tf32(a[fm].x[t]);
                }
#pragma unroll
                for (int fn = 0; fn < 4; fn++) {
                    FragB bfr;
                    wmma::load_matrix_sync(bfr,
                        Bs_f + kk * 8 * B_LD + warp_n * 64 + fn * 16, B_LD);
#pragma unroll
                    for (int t = 0; t < bfr.num_elements; t++)
                        bfr.x[t] = wmma::__float_to_tf32(bfr.x[t]);
#pragma unroll
                    for (int fm = 0; fm < 2; fm++)
                        wmma::mma_sync(acc[fm][fn], a[fm], bfr, acc[fm][fn]);
                }
            }
            __syncthreads();
        }

        // prefetch next n-tile chunk 0 before the epilogue (hides latency)
        if (nt < 7) {
            prefetchA(dsm_u, x, tokBase, 0, tid);
            prefetchB(dsm_u + A_STAGE_B, W1, eb + N_TILE, 0, tid);
            CP_COMMIT();
        }

        // epilogue: tanh + W2 fold per fragment via per-warp smem patch
        const int r = lane & 15;
        const int half = lane >> 4;
#pragma unroll
        for (int fm = 0; fm < 2; fm++) {
#pragma unroll
            for (int fn = 0; fn < 4; fn++) {
                wmma::store_matrix_sync(patch, acc[fm][fn], PATCH_LD, wmma::mem_row_major);
                __syncwarp();
                const int e0 = eb + warp_n * 64 + fn * 16 + half * 8;
                float s = 0.f;
#pragma unroll
                for (int c = 0; c < 8; c++) {
                    float pre = patch[r * PATCH_LD + half * 8 + c] + s_b1[e0 + c];
                    s += tanh_fast(pre) * s_w2[e0 + c];
                }
                s += __shfl_down_sync(0xffffffffu, s, 16);
                if (lane < 16) tokAcc[fm] += s;
                __syncwarp();
            }
        }
    }

    // combine the two warp_n partials per token
    if (lane < 16) {
#pragma unroll
        for (int fm = 0; fm < 2; fm++)
            s_val[warp_n][warp_m * 32 + fm * 16 + lane] = tokAcc[fm];
    }
    __syncthreads();
    if (tid < M_CTA)
        g_valpre[tokBase + tid] = s_val[0][tid] + s_val[1][tid];
}

// ---------------------------------------------------------------------------
// Kernel 2: sigmoid + mask + per-batch normalization; writes att_weights.
// ---------------------------------------------------------------------------
__global__ __launch_bounds__(512) void k_finalize(const float* __restrict__ mask,
                                                  const float* __restrict__ b2,
                                                  float* __restrict__ out_att)
{
    __shared__ float sred[16];
    const int b = blockIdx.x;
    const int j = threadIdx.x;

    float v = g_valpre[b * JJ + j];
    v = 1.f / (1.f + __expf(-(v + b2[0])));
    v *= mask[b * JJ + j];

    float s = v;
#pragma unroll
    for (int o = 16; o; o >>= 1) s += __shfl_xor_sync(0xffffffffu, s, o);
    if ((j & 31) == 0) sred[j >> 5] = s;
    __syncthreads();
    if (j < 16) {
        float t = sred[j];
#pragma unroll
        for (int o = 8; o; o >>= 1) t += __shfl_xor_sync(0xffffu, t, o);
        if (j == 0) sred[0] = t;
    }
    __syncthreads();

    float a = v * (1.f / sred[0]);
    g_att[b * JJ + j] = a;
    out_att[b * JJ + j] = a;
}

// ---------------------------------------------------------------------------
// Kernel 3: pooled[b,d] = sum_j x[b,j,d] * att[b,j]
// ---------------------------------------------------------------------------
__global__ __launch_bounds__(256) void k_pool(const float* __restrict__ x)
{
    __shared__ float sa[JJ];
    const int b = blockIdx.y;
    const int d = blockIdx.x * 256 + threadIdx.x;

    for (int j = threadIdx.x; j < JJ; j += 256) sa[j] = g_att[b * JJ + j];
    __syncthreads();

    float acc = 0.f;
    const float* xb = x + (size_t)b * JJ * DD + d;
#pragma unroll 8
    for (int j = 0; j < JJ; j++) acc += xb[(size_t)j * DD] * sa[j];
    g_pooled[b * DD + d] = acc;
}

// ---------------------------------------------------------------------------
// Kernel 4: output[b,:] = pooled[b,:] @ W3 + b3
// ---------------------------------------------------------------------------
__global__ __launch_bounds__(128) void k_out(const float* __restrict__ W3,
                                             const float* __restrict__ b3,
                                             float* __restrict__ out)
{
    __shared__ float sred[3][4];
    const int b = blockIdx.x;
    const int t = threadIdx.x;

    float a0 = 0.f, a1 = 0.f, a2 = 0.f;
    for (int d = t; d < DD; d += 128) {
        float p = g_pooled[b * DD + d];
        a0 += p * W3[d * 3 + 0];
        a1 += p * W3[d * 3 + 1];
        a2 += p * W3[d * 3 + 2];
    }
#pragma unroll
    for (int o = 16; o; o >>= 1) {
        a0 += __shfl_xor_sync(0xffffffffu, a0, o);
        a1 += __shfl_xor_sync(0xffffffffu, a1, o);
        a2 += __shfl_xor_sync(0xffffffffu, a2, o);
    }
    const int w = t >> 5;
    if ((t & 31) == 0) { sred[0][w] = a0; sred[1][w] = a1; sred[2][w] = a2; }
    __syncthreads();
    if (t == 0) {
        float r0 = 0.f, r1 = 0.f, r2 = 0.f;
#pragma unroll
        for (int k = 0; k < 4; k++) { r0 += sred[0][k]; r1 += sred[1][k]; r2 += sred[2][k]; }
        out[b * 3 + 0] = r0 + b3[0];
        out[b * 3 + 1] = r1 + b3[1];
        out[b * 3 + 2] = r2 + b3[2];
    }
}

// ---------------------------------------------------------------------------
extern "C" void kernel_launch(void* const* d_in, const int* in_sizes, int n_in,
                              void* d_out, int out_size)
{
    const float* x    = (const float*)d_in[0];
    const float* mask = (const float*)d_in[1];
    const float* W1   = (const float*)d_in[2];
    const float* b1   = (const float*)d_in[3];
    const float* W2   = (const float*)d_in[4];
    const float* b2   = (const float*)d_in[5];
    const float* W3   = (const float*)d_in[6];
    const float* b3   = (const float*)d_in[7];
    float* out = (float*)d_out;

    float* out_val = out;            // [64,3]
    float* out_att = out + BB * 3;   // [64,512,1]

    const int smem_bytes = 2 * STAGE_B;   // 70656
    cudaFuncSetAttribute(k_score_mma, cudaFuncAttributeMaxDynamicSharedMemorySize, smem_bytes);

    k_score_mma<<<NTOK / M_CTA, 256, smem_bytes>>>(x, W1, b1, W2);
    k_finalize<<<BB, 512>>>(mask, b2, out_att);
    dim3 gpool(DD / 256, BB);
    k_pool<<<gpool, 256>>>(x);
    k_out<<<BB, 128>>>(W3, b3, out_val);
}

// round 4
// speedup vs baseline: 7.0153x; 3.6037x over previous
#include <cuda_runtime.h>
#include <cuda_fp16.h>
#include <math.h>
#include <mma.h>
#include <cstdint>

using namespace nvcuda;

#define BB 64
#define JJ 512
#define DD 1024
#define NTOK (BB*JJ)

// Scratch (allocation-free rule: __device__ globals)
__device__ float g_valpre[NTOK];
__device__ float g_att[NTOK];
__device__ float g_pooled[BB*DD];
__device__ __half g_xh[(size_t)NTOK * DD];   // 64 MB fp16 copy of x
__device__ __half g_w1h[DD * DD];            // 2 MB fp16 copy of W1

// ---------------------------------------------------------------------------
__device__ __forceinline__ uint32_t smem_u32(const void* p) {
    uint32_t a;
    asm("{ .reg .u64 t; cvta.to.shared.u64 t, %1; cvt.u32.u64 %0, t; }" : "=r"(a) : "l"(p));
    return a;
}
#define CP_ASYNC16(s, g) asm volatile("cp.async.cg.shared.global [%0], [%1], 16;" :: "r"(s), "l"(g) : "memory")
#define CP_COMMIT()      asm volatile("cp.async.commit_group;" ::: "memory")
#define CP_WAIT1()       asm volatile("cp.async.wait_group 1;" ::: "memory")
#define CP_WAIT0()       asm volatile("cp.async.wait_group 0;" ::: "memory")

// accurate tanh via expf (rel err ~1e-6)
__device__ __forceinline__ float tanh_fast(float x) {
    float z = __expf(-2.f * fabsf(x));
    float t = __fdividef(1.f - z, 1.f + z);
    return copysignf(t, x);
}

// ---------------------------------------------------------------------------
// Converters: fp32 -> fp16 (8 elems per thread, vectorized)
// ---------------------------------------------------------------------------
__global__ __launch_bounds__(256) void k_cvt_x(const float* __restrict__ src) {
    size_t i = ((size_t)blockIdx.x * 256 + threadIdx.x) * 8;
    float4 a = *reinterpret_cast<const float4*>(src + i);
    float4 b = *reinterpret_cast<const float4*>(src + i + 4);
    __half2 h0 = __floats2half2_rn(a.x, a.y);
    __half2 h1 = __floats2half2_rn(a.z, a.w);
    __half2 h2 = __floats2half2_rn(b.x, b.y);
    __half2 h3 = __floats2half2_rn(b.z, b.w);
    uint4 o;
    o.x = *(uint32_t*)&h0; o.y = *(uint32_t*)&h1;
    o.z = *(uint32_t*)&h2; o.w = *(uint32_t*)&h3;
    *reinterpret_cast<uint4*>(&g_xh[i]) = o;
}
__global__ __launch_bounds__(256) void k_cvt_w1(const float* __restrict__ src) {
    size_t i = ((size_t)blockIdx.x * 256 + threadIdx.x) * 8;
    float4 a = *reinterpret_cast<const float4*>(src + i);
    float4 b = *reinterpret_cast<const float4*>(src + i + 4);
    __half2 h0 = __floats2half2_rn(a.x, a.y);
    __half2 h1 = __floats2half2_rn(a.z, a.w);
    __half2 h2 = __floats2half2_rn(b.x, b.y);
    __half2 h3 = __floats2half2_rn(b.z, b.w);
    uint4 o;
    o.x = *(uint32_t*)&h0; o.y = *(uint32_t*)&h1;
    o.z = *(uint32_t*)&h2; o.w = *(uint32_t*)&h3;
    *reinterpret_cast<uint4*>(&g_w1h[i]) = o;
}

// ---------------------------------------------------------------------------
// Kernel 1: WMMA fp16 scoring GEMM + fused tanh/W2 epilogue.
// CTA: 128 tokens x 128 e-cols/pass, 8 n-tile passes, K chunks of 64 halves.
// 8 warps (4m x 2n), warp tile 32x64 = 2x4 m16n16k16 fragments.
// ---------------------------------------------------------------------------
#define M_CTA 128
#define N_TILE 128
#define K_CHUNK 64
#define A_LDH 72                               // halves (64 + 8 pad = 16B)
#define B_LDH 136                              // halves (128 + 8 pad)
#define A_STAGE_B (M_CTA * A_LDH * 2)          // 18432
#define B_STAGE_B (K_CHUNK * B_LDH * 2)        // 17408
#define STAGE_B   (A_STAGE_B + B_STAGE_B)      // 35840
#define PATCH_LD 20

typedef wmma::fragment<wmma::matrix_a, 16, 16, 16, __half, wmma::row_major> FragA;
typedef wmma::fragment<wmma::matrix_b, 16, 16, 16, __half, wmma::row_major> FragB;
typedef wmma::fragment<wmma::accumulator, 16, 16, 16, float> FragC;

__device__ __forceinline__ void prefetchA(uint32_t As_u, int tokBase, int kb, int tid) {
    const __half* xh = g_xh;
#pragma unroll
    for (int i = 0; i < 4; i++) {
        int c = tid + i * 256;
        int row = c >> 3, q = c & 7;                       // 8x16B chunks per row
        CP_ASYNC16(As_u + row * (A_LDH * 2) + q * 16,
                   xh + (size_t)(tokBase + row) * DD + kb + q * 8);
    }
}
__device__ __forceinline__ void prefetchB(uint32_t Bs_u, int eb, int kb, int tid) {
    const __half* wh = g_w1h;
#pragma unroll
    for (int i = 0; i < 4; i++) {
        int c = tid + i * 256;
        int row = c >> 4, q = c & 15;                      // 16x16B chunks per row
        CP_ASYNC16(Bs_u + row * (B_LDH * 2) + q * 16,
                   wh + (size_t)(kb + row) * DD + eb + q * 8);
    }
}

__global__ void __launch_bounds__(256, 2)
k_score_mma(const float* __restrict__ b1, const float* __restrict__ W2)
{
    extern __shared__ __align__(16) char dsm[];            // 2 stages
    __shared__ float s_b1[DD];
    __shared__ float s_w2[DD];
    __shared__ __align__(16) float s_patch[8 * 16 * PATCH_LD];
    __shared__ float s_val[2][M_CTA];

    const int tid = threadIdx.x;
    const int wid = tid >> 5;
    const int lane = tid & 31;
    const int warp_m = wid >> 1;          // 0..3
    const int warp_n = wid & 1;           // 0..1
    const int tokBase = blockIdx.x * M_CTA;

    const uint32_t dsm_u = smem_u32(dsm);

    for (int i = tid; i < DD; i += 256) { s_b1[i] = b1[i]; s_w2[i] = W2[i]; }

    float* patch = s_patch + wid * 16 * PATCH_LD;
    float tokAcc[2] = {0.f, 0.f};

    // prologue: n-tile 0, chunk 0 -> stage 0
    prefetchA(dsm_u, tokBase, 0, tid);
    prefetchB(dsm_u + A_STAGE_B, 0, 0, tid);
    CP_COMMIT();

    for (int nt = 0; nt < 8; nt++) {
        const int eb = nt * N_TILE;

        FragC acc[2][4];
#pragma unroll
        for (int fm = 0; fm < 2; fm++)
#pragma unroll
            for (int fn = 0; fn < 4; fn++)
                wmma::fill_fragment(acc[fm][fn], 0.f);

        for (int kc = 0; kc < 16; kc++) {
            const uint32_t st = (uint32_t)(kc & 1) * STAGE_B;
            if (kc < 15) {
                const uint32_t nst = (uint32_t)((kc + 1) & 1) * STAGE_B;
                prefetchA(dsm_u + nst, tokBase, (kc + 1) * K_CHUNK, tid);
                prefetchB(dsm_u + nst + A_STAGE_B, eb, (kc + 1) * K_CHUNK, tid);
                CP_COMMIT();
                CP_WAIT1();
            } else {
                CP_WAIT0();
            }
            __syncthreads();

            const __half* As_h = (const __half*)(dsm + st);
            const __half* Bs_h = (const __half*)(dsm + st + A_STAGE_B);

#pragma unroll
            for (int kk = 0; kk < 4; kk++) {
                FragA a[2];
#pragma unroll
                for (int fm = 0; fm < 2; fm++)
                    wmma::load_matrix_sync(a[fm],
                        As_h + (warp_m * 32 + fm * 16) * A_LDH + kk * 16, A_LDH);
#pragma unroll
                for (int fn = 0; fn < 4; fn++) {
                    FragB bfr;
                    wmma::load_matrix_sync(bfr,
                        Bs_h + kk * 16 * B_LDH + warp_n * 64 + fn * 16, B_LDH);
#pragma unroll
                    for (int fm = 0; fm < 2; fm++)
                        wmma::mma_sync(acc[fm][fn], a[fm], bfr, acc[fm][fn]);
                }
            }
            __syncthreads();
        }

        // prefetch next n-tile chunk 0 before the epilogue (hides latency)
        if (nt < 7) {
            prefetchA(dsm_u, tokBase, 0, tid);
            prefetchB(dsm_u + A_STAGE_B, eb + N_TILE, 0, tid);
            CP_COMMIT();
        }

        // epilogue: tanh + W2 fold per fragment via per-warp smem patch
        const int r = lane & 15;
        const int half_ = lane >> 4;
#pragma unroll
        for (int fm = 0; fm < 2; fm++) {
#pragma unroll
            for (int fn = 0; fn < 4; fn++) {
                wmma::store_matrix_sync(patch, acc[fm][fn], PATCH_LD, wmma::mem_row_major);
                __syncwarp();
                const int e0 = eb + warp_n * 64 + fn * 16 + half_ * 8;
                float s = 0.f;
#pragma unroll
                for (int c = 0; c < 8; c++) {
                    float pre = patch[r * PATCH_LD + half_ * 8 + c] + s_b1[e0 + c];
                    s += tanh_fast(pre) * s_w2[e0 + c];
                }
                s += __shfl_down_sync(0xffffffffu, s, 16);
                if (lane < 16) tokAcc[fm] += s;
                __syncwarp();
            }
        }
    }

    // combine the two warp_n partials per token
    if (lane < 16) {
#pragma unroll
        for (int fm = 0; fm < 2; fm++)
            s_val[warp_n][warp_m * 32 + fm * 16 + lane] = tokAcc[fm];
    }
    __syncthreads();
    if (tid < M_CTA)
        g_valpre[tokBase + tid] = s_val[0][tid] + s_val[1][tid];
}

// ---------------------------------------------------------------------------
// Kernel 2: sigmoid + mask + per-batch normalization; writes att_weights.
// ---------------------------------------------------------------------------
__global__ __launch_bounds__(512) void k_finalize(const float* __restrict__ mask,
                                                  const float* __restrict__ b2,
                                                  float* __restrict__ out_att)
{
    __shared__ float sred[16];
    const int b = blockIdx.x;
    const int j = threadIdx.x;

    float v = g_valpre[b * JJ + j];
    v = 1.f / (1.f + __expf(-(v + b2[0])));
    v *= mask[b * JJ + j];

    float s = v;
#pragma unroll
    for (int o = 16; o; o >>= 1) s += __shfl_xor_sync(0xffffffffu, s, o);
    if ((j & 31) == 0) sred[j >> 5] = s;
    __syncthreads();
    if (j < 16) {
        float t = sred[j];
#pragma unroll
        for (int o = 8; o; o >>= 1) t += __shfl_xor_sync(0xffffu, t, o);
        if (j == 0) sred[0] = t;
    }
    __syncthreads();

    float a = v * (1.f / sred[0]);
    g_att[b * JJ + j] = a;
    out_att[b * JJ + j] = a;
}

// ---------------------------------------------------------------------------
// Kernel 3: pooled[b,d] = sum_j x[b,j,d] * att[b,j]   (fp32 x for accuracy)
// ---------------------------------------------------------------------------
__global__ __launch_bounds__(256) void k_pool(const float* __restrict__ x)
{
    __shared__ float sa[JJ];
    const int b = blockIdx.y;
    const int d = blockIdx.x * 256 + threadIdx.x;

    for (int j = threadIdx.x; j < JJ; j += 256) sa[j] = g_att[b * JJ + j];
    __syncthreads();

    float acc = 0.f;
    const float* xb = x + (size_t)b * JJ * DD + d;
#pragma unroll 8
    for (int j = 0; j < JJ; j++) acc += xb[(size_t)j * DD] * sa[j];
    g_pooled[b * DD + d] = acc;
}

// ---------------------------------------------------------------------------
// Kernel 4: output[b,:] = pooled[b,:] @ W3 + b3
// ---------------------------------------------------------------------------
__global__ __launch_bounds__(128) void k_out(const float* __restrict__ W3,
                                             const float* __restrict__ b3,
                                             float* __restrict__ out)
{
    __shared__ float sred[3][4];
    const int b = blockIdx.x;
    const int t = threadIdx.x;

    float a0 = 0.f, a1 = 0.f, a2 = 0.f;
    for (int d = t; d < DD; d += 128) {
        float p = g_pooled[b * DD + d];
        a0 += p * W3[d * 3 + 0];
        a1 += p * W3[d * 3 + 1];
        a2 += p * W3[d * 3 + 2];
    }
#pragma unroll
    for (int o = 16; o; o >>= 1) {
        a0 += __shfl_xor_sync(0xffffffffu, a0, o);
        a1 += __shfl_xor_sync(0xffffffffu, a1, o);
        a2 += __shfl_xor_sync(0xffffffffu, a2, o);
    }
    const int w = t >> 5;
    if ((t & 31) == 0) { sred[0][w] = a0; sred[1][w] = a1; sred[2][w] = a2; }
    __syncthreads();
    if (t == 0) {
        float r0 = 0.f, r1 = 0.f, r2 = 0.f;
#pragma unroll
        for (int k = 0; k < 4; k++) { r0 += sred[0][k]; r1 += sred[1][k]; r2 += sred[2][k]; }
        out[b * 3 + 0] = r0 + b3[0];
        out[b * 3 + 1] = r1 + b3[1];
        out[b * 3 + 2] = r2 + b3[2];
    }
}

// ---------------------------------------------------------------------------
extern "C" void kernel_launch(void* const* d_in, const int* in_sizes, int n_in,
                              void* d_out, int out_size)
{
    const float* x    = (const float*)d_in[0];
    const float* mask = (const float*)d_in[1];
    const float* W1   = (const float*)d_in[2];
    const float* b1   = (const float*)d_in[3];
    const float* W2   = (const float*)d_in[4];
    const float* b2   = (const float*)d_in[5];
    const float* W3   = (const float*)d_in[6];
    const float* b3   = (const float*)d_in[7];
    float* out = (float*)d_out;

    float* out_val = out;            // [64,3]
    float* out_att = out + BB * 3;   // [64,512,1]

    const int smem_bytes = 2 * STAGE_B;   // 71680
    cudaFuncSetAttribute(k_score_mma, cudaFuncAttributeMaxDynamicSharedMemorySize, smem_bytes);

    k_cvt_x<<<(NTOK * (DD / 8)) / 256, 256>>>(x);          // 16384 blocks
    k_cvt_w1<<<(DD * (DD / 8)) / 256, 256>>>(W1);          // 512 blocks
    k_score_mma<<<NTOK / M_CTA, 256, smem_bytes>>>(b1, W2);
    k_finalize<<<BB, 512>>>(mask, b2, out_att);
    dim3 gpool(DD / 256, BB);
    k_pool<<<gpool, 256>>>(x);
    k_out<<<BB, 128>>>(W3, b3, out_val);
}